// round 5
// baseline (speedup 1.0000x reference)
#include <cuda_runtime.h>
#include <stdint.h>

// ---------------- problem constants ----------------
#define BN 4
#define DD 81
#define KK 2048
#define ND 4

// ---------------- GEMM config ----------------
#define MPAD 96             // padded M (81 -> 96)
#define NTILE 128           // n per CTA
#define KCH 64              // k (p) per stage
#define KSPLIT 2
#define KSEG (KK / KSPLIT)  // 1024
#define NSTG (KSEG / KCH)   // 16
#define BSTRIDE 136         // smem f32 row stride for B (conflict-free frag reads)
#define ABYTES (KCH / 8 * 6 * 512)      // 24576: frag-packed A stage
#define BBYTES (KCH * BSTRIDE * 4)      // 34816
#define STGB (ABYTES + BBYTES)          // 59392
#define DYN_SMEM (2 * STGB)             // 118784

// ---------------- static device scratch ----------------
__device__ float g_pp[(size_t)BN * KK * 12];              // packed params {mu[4], sig2[4], w, pad[3]}
__device__ float g_rinv[BN * KK];
__device__ float g_A[(size_t)BN * (KK / 8) * 6 * 128];    // frag-packed A [b][kb][mfg][lane*4]
__device__ float g_part[(size_t)KSPLIT * BN * MPAD * KK]; // split-K partials

// ---------------- helpers ----------------
__device__ __forceinline__ float to_tf32(float v) {
    float r;
    asm("cvt.rna.tf32.f32 %0, %1;" : "=f"(r) : "f"(v));
    return r;
}
__device__ __forceinline__ float frcp(float v) {
    float r;
    asm("rcp.approx.ftz.f32 %0, %1;" : "=f"(r) : "f"(v));
    return r;
}
__device__ __forceinline__ uint32_t smem_u32(const void* p) {
    uint32_t a;
    asm("{ .reg .u64 t; cvta.to.shared.u64 t, %1; cvt.u32.u64 %0, t; }" : "=r"(a) : "l"(p));
    return a;
}
__device__ __forceinline__ void cpasync16(uint32_t dst, const void* src) {
    asm volatile("cp.async.cg.shared.global [%0], [%1], 16;" :: "r"(dst), "l"(src));
}
#define CP_COMMIT() asm volatile("cp.async.commit_group;" ::: "memory")
#define CP_WAIT(n)  asm volatile("cp.async.wait_group %0;" :: "n"(n) : "memory")

__device__ __forceinline__ void mma_tf32(float* d, const uint32_t* a, const uint32_t* b) {
    asm volatile(
        "mma.sync.aligned.m16n8k8.row.col.f32.tf32.tf32.f32 "
        "{%0,%1,%2,%3}, {%4,%5,%6,%7}, {%8,%9}, {%0,%1,%2,%3};"
        : "+f"(d[0]), "+f"(d[1]), "+f"(d[2]), "+f"(d[3])
        : "r"(a[0]), "r"(a[1]), "r"(a[2]), "r"(a[3]), "r"(b[0]), "r"(b[1]));
}

// ---------------- K1: pack per-component params ----------------
__global__ void prep_kernel(const float* __restrict__ pi,
                            const float* __restrict__ mu,
                            const float* __restrict__ sig) {
    int i = blockIdx.x * 256 + threadIdx.x;
    if (i >= BN * KK) return;
    int b = i / KK, k = i - b * KK;
    float mv[4], sv[4], prod = 1.0f;
#pragma unroll
    for (int n = 0; n < ND; n++) {
        mv[n] = mu[(b * ND + n) * KK + k];
        float s = sig[(b * ND + n) * KK + k];
        sv[n] = s * s;
        prod *= s;
    }
    float* dst = g_pp + (size_t)i * 12;
    *(float4*)(dst + 0) = make_float4(mv[0], mv[1], mv[2], mv[3]);
    *(float4*)(dst + 4) = make_float4(sv[0], sv[1], sv[2], sv[3]);
    *(float4*)(dst + 8) = make_float4(pi[i] * prod, 0.0f, 0.0f, 0.0f);
}

// ---------------- K2: row sums only (no lh store) ----------------
// 16 p rows per block, 256 threads.
__global__ __launch_bounds__(256) void rowsum_kernel() {
    int b = blockIdx.y;
    int p0 = blockIdx.x * 16;

    __shared__ float smup[16][4];
    if (threadIdx.x < 64) {
        int j = threadIdx.x >> 2, n = threadIdx.x & 3;
        smup[j][n] = g_pp[(size_t)(b * KK + p0 + j) * 12 + n];
    }
    __syncthreads();

    float mp[16][4];
#pragma unroll
    for (int j = 0; j < 16; j++)
#pragma unroll
        for (int n = 0; n < 4; n++) mp[j][n] = smup[j][n];

    float acc[16];
#pragma unroll
    for (int j = 0; j < 16; j++) acc[j] = 0.0f;

    for (int m = threadIdx.x; m < KK; m += 256) {
        const float* c = g_pp + (size_t)(b * KK + m) * 12;
        float4 cm = *(const float4*)c;
        float4 cs = *(const float4*)(c + 4);
        float w = c[8];
#pragma unroll
        for (int j = 0; j < 16; j++) {
            float d0 = mp[j][0] - cm.x;
            float d1 = mp[j][1] - cm.y;
            float d2 = mp[j][2] - cm.z;
            float d3 = mp[j][3] - cm.w;
            float q = (fmaf(d0, d0, cs.x) * fmaf(d1, d1, cs.y)) *
                      (fmaf(d2, d2, cs.z) * fmaf(d3, d3, cs.w));
            acc[j] = fmaf(w, frcp(q), acc[j]);
        }
    }

    __shared__ float red[8][17];
    int lane = threadIdx.x & 31, wid = threadIdx.x >> 5;
#pragma unroll
    for (int j = 0; j < 16; j++) {
        float v = acc[j];
#pragma unroll
        for (int o = 16; o > 0; o >>= 1) v += __shfl_xor_sync(0xffffffffu, v, o);
        if (lane == 0) red[wid][j] = v;
    }
    __syncthreads();
    if (threadIdx.x < 16) {
        float s = 0.0f;
#pragma unroll
        for (int w = 0; w < 8; w++) s += red[w][threadIdx.x];
        g_rinv[b * KK + p0 + threadIdx.x] = 1.0f / s;
    }
}

// ---------------- K3: A -> MMA-fragment-packed layout ----------------
__global__ void aprep_kernel(const float* __restrict__ x) {
    int kb = blockIdx.x, b = blockIdx.y;
    int t = threadIdx.x;           // 0..191
    int mfg = t >> 5, lane = t & 31;
    int g = lane >> 2, c = lane & 3;
    int m = mfg * 16 + g;
    int k = kb * 8 + c;

    float r0 = g_rinv[b * KK + k];
    float r1 = g_rinv[b * KK + k + 4];
    const float* xb = x + (size_t)b * DD * KK;

    float4 v = make_float4(0.0f, 0.0f, 0.0f, 0.0f);
    if (m < DD) {
        v.x = to_tf32(xb[(size_t)m * KK + k] * r0);
        v.z = to_tf32(xb[(size_t)m * KK + k + 4] * r1);
    }
    if (m + 8 < DD) {
        v.y = to_tf32(xb[(size_t)(m + 8) * KK + k] * r0);
        v.w = to_tf32(xb[(size_t)(m + 8) * KK + k + 4] * r1);
    }
    *(float4*)(g_A + (((size_t)(b * 256 + kb) * 6 + mfg) * 128 + lane * 4)) = v;
}

// ---------------- K4: fused GEMM — producers generate B (lh) in smem ----------------
// grid (KK/NTILE, KSPLIT, BN), 512 threads: warps 0-11 MMA (3Mx4N), warps 12-15 producers.
__global__ __launch_bounds__(512, 1) void gemm_fused() {
    extern __shared__ char dsm[];
    uint32_t sbase = smem_u32(dsm);

    int tid = threadIdx.x, wid = tid >> 5, lane = tid & 31;
    int nt = blockIdx.x, ks = blockIdx.y, b = blockIdx.z;
    int n0 = nt * NTILE;
    int pbase0 = ks * KSEG;
    int kb0 = ks * (KSEG / 8);

    // ---- producer state (warps 12-15): per-m params in registers ----
    int ml = tid & 127;                     // producer's n-column (tid-384 for wid>=12)
    float4 mu_m = make_float4(0, 0, 0, 0), s_m = make_float4(0, 0, 0, 0);
    float w_m = 0.0f;
    if (wid >= 12) {
        const float* cp = g_pp + (size_t)(b * KK + n0 + ml) * 12;
        mu_m = *(const float4*)cp;
        s_m  = *(const float4*)(cp + 4);
        w_m  = cp[8];
    }

    auto prod_stage = [&](int s) {
        int buf = s & 1;
        uint32_t abase = sbase + buf * STGB;
        const float4* srcA = (const float4*)(g_A + (size_t)(b * 256 + kb0 + s * 8) * 6 * 128);
#pragma unroll
        for (int e = 0; e < 12; e++)
            cpasync16(abase + (uint32_t)(ml + 128 * e) * 16u, srcA + ml + 128 * e);
        CP_COMMIT();

        float* Bs = (float*)(dsm + buf * STGB + ABYTES);
        const float* pc = g_pp + (size_t)(b * KK + pbase0 + s * KCH) * 12;
#pragma unroll 4
        for (int p = 0; p < KCH; p++) {
            float4 mp = *(const float4*)(pc + (size_t)p * 12);
            float d0 = mp.x - mu_m.x;
            float d1 = mp.y - mu_m.y;
            float d2 = mp.z - mu_m.z;
            float d3 = mp.w - mu_m.w;
            float q = (fmaf(d0, d0, s_m.x) * fmaf(d1, d1, s_m.y)) *
                      (fmaf(d2, d2, s_m.z) * fmaf(d3, d3, s_m.w));
            Bs[p * BSTRIDE + ml] = to_tf32(w_m * frcp(q));
        }
        CP_WAIT(0);
    };

    // ---- MMA state ----
    int warpM = wid >> 2, warpN = wid & 3;  // valid for wid<12
    int nbase = warpN * 32;
    int g = lane >> 2, c = lane & 3;

    float acc[2][4][4];
#pragma unroll
    for (int i = 0; i < 2; i++)
#pragma unroll
        for (int j = 0; j < 4; j++)
#pragma unroll
            for (int q = 0; q < 4; q++) acc[i][j][q] = 0.0f;

    // prologue: stage 0
    if (wid >= 12) prod_stage(0);
    __syncthreads();

    for (int s = 0; s < NSTG; s++) {
        if (wid < 12) {
            int buf = s & 1;
            const float4* A4 = (const float4*)(dsm + buf * STGB);
            const float* B = (const float*)(dsm + buf * STGB + ABYTES);
#pragma unroll
            for (int kb = 0; kb < KCH / 8; kb++) {
                uint32_t af[2][4], bf[4][2];
#pragma unroll
                for (int mf = 0; mf < 2; mf++) {
                    float4 av = A4[(kb * 6 + warpM * 2 + mf) * 32 + lane];
                    af[mf][0] = __float_as_uint(av.x);
                    af[mf][1] = __float_as_uint(av.y);
                    af[mf][2] = __float_as_uint(av.z);
                    af[mf][3] = __float_as_uint(av.w);
                }
                const float* Br0 = B + (kb * 8 + c) * BSTRIDE;
                const float* Br1 = B + (kb * 8 + c + 4) * BSTRIDE;
#pragma unroll
                for (int nf = 0; nf < 4; nf++) {
                    int n0i = nbase + nf * 8 + g;
                    bf[nf][0] = __float_as_uint(Br0[n0i]);
                    bf[nf][1] = __float_as_uint(Br1[n0i]);
                }
#pragma unroll
                for (int mf = 0; mf < 2; mf++)
#pragma unroll
                    for (int nf = 0; nf < 4; nf++)
                        mma_tf32(acc[mf][nf], af[mf], bf[nf]);
            }
        } else if (s + 1 < NSTG) {
            prod_stage(s + 1);
        }
        __syncthreads();
    }

    // epilogue: write partials (MMA warps only)
    if (wid < 12) {
        float* pp = g_part + ((size_t)(ks * BN + b) * MPAD) * KK + n0;
        int tig = lane & 3;
#pragma unroll
        for (int mf = 0; mf < 2; mf++) {
            int r0 = warpM * 32 + mf * 16 + g;
#pragma unroll
            for (int nf = 0; nf < 4; nf++) {
                int cc = nbase + nf * 8 + tig * 2;
                *(float2*)(pp + (size_t)r0 * KK + cc)       = make_float2(acc[mf][nf][0], acc[mf][nf][1]);
                *(float2*)(pp + (size_t)(r0 + 8) * KK + cc) = make_float2(acc[mf][nf][2], acc[mf][nf][3]);
            }
        }
    }
}

// ---------------- K5: deterministic split-K reduce (float4) ----------------
__global__ void reduce_kernel(float* __restrict__ y) {
    int i = blockIdx.x * 256 + threadIdx.x;   // float4 index
    const int total = BN * DD * KK / 4;
    if (i >= total) return;
    int e = i * 4;
    int b = e / (DD * KK);
    int r = e - b * (DD * KK);
    int d = r / KK;
    int m = r - d * KK;
    size_t o = (((size_t)b * MPAD + d) * KK + m) / 4;
    const float4* p0 = (const float4*)g_part;
    const float4* p1 = (const float4*)(g_part + (size_t)BN * MPAD * KK);
    float4 a = p0[o], bb = p1[o];
    ((float4*)y)[i] = make_float4(a.x + bb.x, a.y + bb.y, a.z + bb.z, a.w + bb.w);
}

// ---------------- launch ----------------
extern "C" void kernel_launch(void* const* d_in, const int* in_sizes, int n_in,
                              void* d_out, int out_size) {
    const float* x   = (const float*)d_in[0];  // (B, D, K)
    const float* pi  = (const float*)d_in[1];  // (B, 1, K)
    const float* mu  = (const float*)d_in[2];  // (B, ND, K)
    const float* sig = (const float*)d_in[3];  // (B, ND, K)
    float* y = (float*)d_out;                  // (B, D, K)

    cudaFuncSetAttribute(gemm_fused, cudaFuncAttributeMaxDynamicSharedMemorySize, DYN_SMEM);

    prep_kernel<<<(BN * KK + 255) / 256, 256>>>(pi, mu, sig);
    rowsum_kernel<<<dim3(KK / 16, BN), 256>>>();
    aprep_kernel<<<dim3(KK / 8, BN), 192>>>(x);
    gemm_fused<<<dim3(KK / NTILE, KSPLIT, BN), 512, DYN_SMEM>>>();
    reduce_kernel<<<(BN * DD * KK / 4 + 255) / 256, 256>>>(y);
}

// round 6
// speedup vs baseline: 1.2979x; 1.2979x over previous
#include <cuda_runtime.h>
#include <stdint.h>

// ---------------- problem constants ----------------
#define BN 4
#define DD 81
#define KK 2048
#define ND 4

// ---------------- fused GEMM config ----------------
#define MPAD 96             // padded M (81 -> 96)
#define NTILE 64            // n (components) per CTA
#define KCH 64              // k (p points) per stage
#define NSTG (KK / KCH)     // 32 stages, full K per CTA (no split-K)
#define BSTRIDE 72          // smem f32 row stride for B (72%32=8 -> conflict-free frags)
#define ABYTES 24576        // (KCH/8)*6*512 frag-packed A stage
#define PBYTES 1024         // 64 x float4 mu_p
#define APB (ABYTES + PBYTES)       // 25600, triple buffered
#define BBYTES (KCH * BSTRIDE * 4)  // 18432, double buffered
#define BBASE (3 * APB)             // 76800
#define DYN_SMEM (BBASE + 2 * BBYTES)  // 113664

// ---------------- static device scratch ----------------
__device__ float  g_pp[(size_t)BN * KK * 12];           // {mu[4], sig2[4], w, pad[3]}
__device__ float4 g_mu4[BN * KK];                       // compact mu rows
__device__ float  g_rinv[BN * KK];
__device__ float  g_A[(size_t)BN * (KK / 8) * 6 * 128]; // frag-packed A

// ---------------- helpers ----------------
typedef unsigned long long ull;
__device__ __forceinline__ float to_tf32(float v) {
    float r; asm("cvt.rna.tf32.f32 %0, %1;" : "=f"(r) : "f"(v)); return r;
}
__device__ __forceinline__ float frcp(float v) {
    float r; asm("rcp.approx.ftz.f32 %0, %1;" : "=f"(r) : "f"(v)); return r;
}
__device__ __forceinline__ ull pack2(float lo, float hi) {
    ull r; asm("mov.b64 %0, {%1, %2};" : "=l"(r) : "f"(lo), "f"(hi)); return r;
}
__device__ __forceinline__ ull splat2(float v) {
    ull r; asm("mov.b64 %0, {%1, %1};" : "=l"(r) : "f"(v)); return r;
}
__device__ __forceinline__ void unpack2(ull v, float& lo, float& hi) {
    asm("mov.b64 {%0, %1}, %2;" : "=f"(lo), "=f"(hi) : "l"(v));
}
__device__ __forceinline__ ull add2(ull a, ull b) {
    ull r; asm("add.rn.f32x2 %0, %1, %2;" : "=l"(r) : "l"(a), "l"(b)); return r;
}
__device__ __forceinline__ ull mul2(ull a, ull b) {
    ull r; asm("mul.rn.f32x2 %0, %1, %2;" : "=l"(r) : "l"(a), "l"(b)); return r;
}
__device__ __forceinline__ ull fma2(ull a, ull b, ull c) {
    ull r; asm("fma.rn.f32x2 %0, %1, %2, %3;" : "=l"(r) : "l"(a), "l"(b), "l"(c)); return r;
}
__device__ __forceinline__ uint32_t smem_u32(const void* p) {
    uint32_t a;
    asm("{ .reg .u64 t; cvta.to.shared.u64 t, %1; cvt.u32.u64 %0, t; }" : "=r"(a) : "l"(p));
    return a;
}
__device__ __forceinline__ void cpasync16(uint32_t dst, const void* src) {
    asm volatile("cp.async.cg.shared.global [%0], [%1], 16;" :: "r"(dst), "l"(src));
}
#define CP_COMMIT() asm volatile("cp.async.commit_group;" ::: "memory")
#define CP_WAIT(n)  asm volatile("cp.async.wait_group %0;" :: "n"(n) : "memory")

__device__ __forceinline__ void mma_tf32(float* d, const uint32_t* a, const uint32_t* b) {
    asm volatile(
        "mma.sync.aligned.m16n8k8.row.col.f32.tf32.tf32.f32 "
        "{%0,%1,%2,%3}, {%4,%5,%6,%7}, {%8,%9}, {%0,%1,%2,%3};"
        : "+f"(d[0]), "+f"(d[1]), "+f"(d[2]), "+f"(d[3])
        : "r"(a[0]), "r"(a[1]), "r"(a[2]), "r"(a[3]), "r"(b[0]), "r"(b[1]));
}

// ---------------- K1: pack params ----------------
__global__ void prep_kernel(const float* __restrict__ pi,
                            const float* __restrict__ mu,
                            const float* __restrict__ sig) {
    int i = blockIdx.x * 256 + threadIdx.x;
    if (i >= BN * KK) return;
    int b = i / KK, k = i - b * KK;
    float mv[4], sv[4], prod = 1.0f;
#pragma unroll
    for (int n = 0; n < ND; n++) {
        mv[n] = mu[(b * ND + n) * KK + k];
        float s = sig[(b * ND + n) * KK + k];
        sv[n] = s * s;
        prod *= s;
    }
    float* dst = g_pp + (size_t)i * 12;
    *(float4*)(dst + 0) = make_float4(mv[0], mv[1], mv[2], mv[3]);
    *(float4*)(dst + 4) = make_float4(sv[0], sv[1], sv[2], sv[3]);
    *(float4*)(dst + 8) = make_float4(pi[i] * prod, 0.0f, 0.0f, 0.0f);
    g_mu4[i] = make_float4(mv[0], mv[1], mv[2], mv[3]);
}

// ---------------- K2: row sums (f32x2-packed, 16 p rows / block) ----------------
__global__ __launch_bounds__(256) void rowsum_kernel() {
    int b = blockIdx.y;
    int p0 = blockIdx.x * 16;
    int tid = threadIdx.x;

    __shared__ float smu[16][4];
    if (tid < 16) {
        float4 v = g_mu4[b * KK + p0 + tid];
        smu[tid][0] = v.x; smu[tid][1] = v.y; smu[tid][2] = v.z; smu[tid][3] = v.w;
    }
    __syncthreads();

    ull muPP[8][4];
#pragma unroll
    for (int j = 0; j < 8; j++)
#pragma unroll
        for (int n = 0; n < 4; n++) muPP[j][n] = pack2(smu[2 * j][n], smu[2 * j + 1][n]);

    float acc[16];
#pragma unroll
    for (int j = 0; j < 16; j++) acc[j] = 0.0f;

    for (int m = tid; m < KK; m += 256) {
        const float* c = g_pp + (size_t)(b * KK + m) * 12;
        float4 cm = *(const float4*)c;
        float4 cs = *(const float4*)(c + 4);
        float w = c[8];
        ull nm0 = splat2(-cm.x), nm1 = splat2(-cm.y), nm2 = splat2(-cm.z), nm3 = splat2(-cm.w);
        ull s0 = splat2(cs.x), s1 = splat2(cs.y), s2 = splat2(cs.z), s3 = splat2(cs.w);
#pragma unroll
        for (int j = 0; j < 8; j++) {
            ull d0 = add2(muPP[j][0], nm0);
            ull d1 = add2(muPP[j][1], nm1);
            ull d2 = add2(muPP[j][2], nm2);
            ull d3 = add2(muPP[j][3], nm3);
            ull q = mul2(mul2(fma2(d0, d0, s0), fma2(d1, d1, s1)),
                         mul2(fma2(d2, d2, s2), fma2(d3, d3, s3)));
            float ql, qh; unpack2(q, ql, qh);
            acc[2 * j]     = fmaf(w, frcp(ql), acc[2 * j]);
            acc[2 * j + 1] = fmaf(w, frcp(qh), acc[2 * j + 1]);
        }
    }

    __shared__ float red[8][17];
    int lane = tid & 31, wid = tid >> 5;
#pragma unroll
    for (int j = 0; j < 16; j++) {
        float v = acc[j];
#pragma unroll
        for (int o = 16; o > 0; o >>= 1) v += __shfl_xor_sync(0xffffffffu, v, o);
        if (lane == 0) red[wid][j] = v;
    }
    __syncthreads();
    if (tid < 16) {
        float s = 0.0f;
#pragma unroll
        for (int w = 0; w < 8; w++) s += red[w][tid];
        g_rinv[b * KK + p0 + tid] = 1.0f / s;
    }
}

// ---------------- K3: A -> MMA-fragment-packed layout ----------------
__global__ void aprep_kernel(const float* __restrict__ x) {
    int kb = blockIdx.x, b = blockIdx.y;
    int t = threadIdx.x;           // 0..191
    int mfg = t >> 5, lane = t & 31;
    int g = lane >> 2, c = lane & 3;
    int m = mfg * 16 + g;
    int k = kb * 8 + c;

    float r0 = g_rinv[b * KK + k];
    float r1 = g_rinv[b * KK + k + 4];
    const float* xb = x + (size_t)b * DD * KK;

    float4 v = make_float4(0.0f, 0.0f, 0.0f, 0.0f);
    if (m < DD) {
        v.x = to_tf32(xb[(size_t)m * KK + k] * r0);
        v.z = to_tf32(xb[(size_t)m * KK + k + 4] * r1);
    }
    if (m + 8 < DD) {
        v.y = to_tf32(xb[(size_t)(m + 8) * KK + k] * r0);
        v.w = to_tf32(xb[(size_t)(m + 8) * KK + k + 4] * r1);
    }
    *(float4*)(g_A + (((size_t)(b * 256 + kb) * 6 + mfg) * 128 + lane * 4)) = v;
}

// ---------------- K4: homogeneous fused GEMM ----------------
// grid (KK/NTILE, BN) = (32, 4), 512 threads. All warps gen B then MMA.
// Warp grid 2M x 8N; warp tile 48 x 8. Gen: warp w covers p rows [4w,4w+4), lanes = 32 m-pairs.
__global__ __launch_bounds__(512, 1) void gemm_fused(float* __restrict__ y) {
    extern __shared__ char dsm[];
    uint32_t sbase = smem_u32(dsm);

    int tid = threadIdx.x, wid = tid >> 5, lane = tid & 31;
    int n0 = blockIdx.x * NTILE, b = blockIdx.y;

    // ---- per-thread gen params: m-pair columns (n0+2*lane, n0+2*lane+1) ----
    ull nmu[4], s2[4];
    float w0, w1;
    {
        const float* cp = g_pp + (size_t)(b * KK + n0 + 2 * lane) * 12;
#pragma unroll
        for (int n = 0; n < 4; n++) {
            nmu[n] = pack2(-cp[n], -cp[12 + n]);
            s2[n]  = pack2(cp[4 + n], cp[16 + n]);
        }
        w0 = cp[8]; w1 = cp[20];
    }

    // ---- MMA state ----
    int warpM = wid >> 3, warpN = wid & 7;
    int nbase = warpN * 8;
    int g = lane >> 2, c = lane & 3;
    float acc[3][4];
#pragma unroll
    for (int i = 0; i < 3; i++)
#pragma unroll
        for (int q = 0; q < 4; q++) acc[i][q] = 0.0f;

    const float4* gA = (const float4*)(g_A + (size_t)b * 256 * 6 * 128);
    const float4* gP = &g_mu4[b * KK];

    auto cp_stage = [&](int s) {
        uint32_t ab = sbase + (uint32_t)(s % 3) * APB;
        const float4* srcA = gA + (size_t)s * 1536;
#pragma unroll
        for (int e = 0; e < 3; e++) {
            int i = tid + 512 * e;
            cpasync16(ab + (uint32_t)i * 16u, srcA + i);
        }
        if (tid < 64)
            cpasync16(ab + ABYTES + (uint32_t)tid * 16u, gP + s * 64 + tid);
        CP_COMMIT();
    };

    auto gen = [&](int s) {
        float* Bs = (float*)(dsm + BBASE + (size_t)(s & 1) * BBYTES);
        const float* P = (const float*)(dsm + (size_t)(s % 3) * APB + ABYTES);
#pragma unroll
        for (int i = 0; i < 4; i++) {
            int p = wid * 4 + i;
            float4 mp = *(const float4*)(P + p * 4);
            ull d0 = add2(splat2(mp.x), nmu[0]);
            ull d1 = add2(splat2(mp.y), nmu[1]);
            ull d2 = add2(splat2(mp.z), nmu[2]);
            ull d3 = add2(splat2(mp.w), nmu[3]);
            ull q = mul2(mul2(fma2(d0, d0, s2[0]), fma2(d1, d1, s2[1])),
                         mul2(fma2(d2, d2, s2[2]), fma2(d3, d3, s2[3])));
            float ql, qh; unpack2(q, ql, qh);
            float l0 = to_tf32(w0 * frcp(ql));
            float l1 = to_tf32(w1 * frcp(qh));
            *(float2*)(Bs + p * BSTRIDE + 2 * lane) = make_float2(l0, l1);
        }
    };

    auto mma_stage = [&](int s) {
        const float4* A4 = (const float4*)(dsm + (size_t)(s % 3) * APB);
        const float* B = (const float*)(dsm + BBASE + (size_t)(s & 1) * BBYTES);
#pragma unroll
        for (int kb = 0; kb < 8; kb++) {
            uint32_t af[3][4], bf[2];
#pragma unroll
            for (int mf = 0; mf < 3; mf++) {
                float4 av = A4[(kb * 6 + warpM * 3 + mf) * 32 + lane];
                af[mf][0] = __float_as_uint(av.x);
                af[mf][1] = __float_as_uint(av.y);
                af[mf][2] = __float_as_uint(av.z);
                af[mf][3] = __float_as_uint(av.w);
            }
            bf[0] = __float_as_uint(B[(kb * 8 + c) * BSTRIDE + nbase + g]);
            bf[1] = __float_as_uint(B[(kb * 8 + c + 4) * BSTRIDE + nbase + g]);
#pragma unroll
            for (int mf = 0; mf < 3; mf++)
                mma_tf32(acc[mf], af[mf], bf);
        }
    };

    // ---- prologue ----
    cp_stage(0);
    cp_stage(1);
    CP_WAIT(1);
    __syncthreads();
    gen(0);
    CP_WAIT(0);
    __syncthreads();

    // ---- main loop: cp(s+2) || gen(s+1) || MMA(s), one barrier per stage ----
    for (int s = 0; s < NSTG; s++) {
        if (s + 2 < NSTG) cp_stage(s + 2);
        if (s + 1 < NSTG) gen(s + 1);
        mma_stage(s);
        CP_WAIT(0);
        __syncthreads();
    }

    // ---- epilogue: write y directly ----
    float* yb = y + (size_t)b * DD * KK + n0;
    int tig = lane & 3;
#pragma unroll
    for (int mf = 0; mf < 3; mf++) {
        int r0 = warpM * 48 + mf * 16 + g;
        int cc = nbase + tig * 2;
        if (r0 < DD)
            *(float2*)(yb + (size_t)r0 * KK + cc) = make_float2(acc[mf][0], acc[mf][1]);
        if (r0 + 8 < DD)
            *(float2*)(yb + (size_t)(r0 + 8) * KK + cc) = make_float2(acc[mf][2], acc[mf][3]);
    }
}

// ---------------- launch ----------------
extern "C" void kernel_launch(void* const* d_in, const int* in_sizes, int n_in,
                              void* d_out, int out_size) {
    const float* x   = (const float*)d_in[0];  // (B, D, K)
    const float* pi  = (const float*)d_in[1];  // (B, 1, K)
    const float* mu  = (const float*)d_in[2];  // (B, ND, K)
    const float* sig = (const float*)d_in[3];  // (B, ND, K)
    float* y = (float*)d_out;                  // (B, D, K)

    cudaFuncSetAttribute(gemm_fused, cudaFuncAttributeMaxDynamicSharedMemorySize, DYN_SMEM);

    prep_kernel<<<(BN * KK + 255) / 256, 256>>>(pi, mu, sig);
    rowsum_kernel<<<dim3(KK / 16, BN), 256>>>();
    aprep_kernel<<<dim3(KK / 8, BN), 192>>>(x);
    gemm_fused<<<dim3(KK / NTILE, BN), 512, DYN_SMEM>>>(y);
}

// round 7
// speedup vs baseline: 1.8072x; 1.3924x over previous
#include <cuda_runtime.h>
#include <stdint.h>

// ---------------- problem constants ----------------
#define BN 4
#define DD 81
#define KK 2048
#define ND 4

// ---------------- fused GEMM config ----------------
#define MPAD 96             // padded M (81 -> 96)
#define NTILE 256           // n (components) per CTA
#define KCH 64              // k (p points) per stage
#define KSPLIT 4
#define KSEG (KK / KSPLIT)  // 512
#define NSTG (KSEG / KCH)   // 8 stages
#define BSTRIDE 264         // smem f32 row stride for B (264*4 mod 128 = 32 -> conflict-free)
#define ABYTES 24576        // (KCH/8)*6*512 frag-packed A stage
#define PBYTES 1024         // 64 x float4 mu_p
#define APB (ABYTES + PBYTES)        // 25600, triple buffered
#define BBYTES (KCH * BSTRIDE * 4)   // 67584, double buffered
#define BBASE (3 * APB)              // 76800
#define DYN_SMEM (BBASE + 2 * BBYTES)  // 211968

// ---------------- static device scratch ----------------
__device__ float  g_pp[(size_t)BN * KK * 12];           // {mu[4], sig2[4], w, pad[3]}
__device__ float4 g_mu4[BN * KK];                       // compact mu rows
__device__ float  g_rinv[BN * KK];
__device__ float  g_A[(size_t)BN * (KK / 8) * 6 * 128]; // frag-packed A
__device__ float  g_part[(size_t)KSPLIT * BN * MPAD * KK]; // split-K partials (12.6MB)

// ---------------- helpers ----------------
typedef unsigned long long ull;
__device__ __forceinline__ float to_tf32(float v) {
    float r; asm("cvt.rna.tf32.f32 %0, %1;" : "=f"(r) : "f"(v)); return r;
}
__device__ __forceinline__ float frcp(float v) {
    float r; asm("rcp.approx.ftz.f32 %0, %1;" : "=f"(r) : "f"(v)); return r;
}
__device__ __forceinline__ ull pack2(float lo, float hi) {
    ull r; asm("mov.b64 %0, {%1, %2};" : "=l"(r) : "f"(lo), "f"(hi)); return r;
}
__device__ __forceinline__ ull splat2(float v) {
    ull r; asm("mov.b64 %0, {%1, %1};" : "=l"(r) : "f"(v)); return r;
}
__device__ __forceinline__ void unpack2(ull v, float& lo, float& hi) {
    asm("mov.b64 {%0, %1}, %2;" : "=f"(lo), "=f"(hi) : "l"(v));
}
__device__ __forceinline__ ull add2(ull a, ull b) {
    ull r; asm("add.rn.f32x2 %0, %1, %2;" : "=l"(r) : "l"(a), "l"(b)); return r;
}
__device__ __forceinline__ ull mul2(ull a, ull b) {
    ull r; asm("mul.rn.f32x2 %0, %1, %2;" : "=l"(r) : "l"(a), "l"(b)); return r;
}
__device__ __forceinline__ ull fma2(ull a, ull b, ull c) {
    ull r; asm("fma.rn.f32x2 %0, %1, %2, %3;" : "=l"(r) : "l"(a), "l"(b), "l"(c)); return r;
}
__device__ __forceinline__ uint32_t smem_u32(const void* p) {
    uint32_t a;
    asm("{ .reg .u64 t; cvta.to.shared.u64 t, %1; cvt.u32.u64 %0, t; }" : "=r"(a) : "l"(p));
    return a;
}
__device__ __forceinline__ void cpasync16(uint32_t dst, const void* src) {
    asm volatile("cp.async.cg.shared.global [%0], [%1], 16;" :: "r"(dst), "l"(src));
}
#define CP_COMMIT() asm volatile("cp.async.commit_group;" ::: "memory")
#define CP_WAIT(n)  asm volatile("cp.async.wait_group %0;" :: "n"(n) : "memory")

__device__ __forceinline__ void mma_tf32(float* d, const uint32_t* a, const uint32_t* b) {
    asm volatile(
        "mma.sync.aligned.m16n8k8.row.col.f32.tf32.tf32.f32 "
        "{%0,%1,%2,%3}, {%4,%5,%6,%7}, {%8,%9}, {%0,%1,%2,%3};"
        : "+f"(d[0]), "+f"(d[1]), "+f"(d[2]), "+f"(d[3])
        : "r"(a[0]), "r"(a[1]), "r"(a[2]), "r"(a[3]), "r"(b[0]), "r"(b[1]));
}

// ---------------- K1: pack params ----------------
__global__ void prep_kernel(const float* __restrict__ pi,
                            const float* __restrict__ mu,
                            const float* __restrict__ sig) {
    int i = blockIdx.x * 256 + threadIdx.x;
    if (i >= BN * KK) return;
    int b = i / KK, k = i - b * KK;
    float mv[4], sv[4], prod = 1.0f;
#pragma unroll
    for (int n = 0; n < ND; n++) {
        mv[n] = mu[(b * ND + n) * KK + k];
        float s = sig[(b * ND + n) * KK + k];
        sv[n] = s * s;
        prod *= s;
    }
    float* dst = g_pp + (size_t)i * 12;
    *(float4*)(dst + 0) = make_float4(mv[0], mv[1], mv[2], mv[3]);
    *(float4*)(dst + 4) = make_float4(sv[0], sv[1], sv[2], sv[3]);
    *(float4*)(dst + 8) = make_float4(pi[i] * prod, 0.0f, 0.0f, 0.0f);
    g_mu4[i] = make_float4(mv[0], mv[1], mv[2], mv[3]);
}

// ---------------- K2: row sums (f32x2-packed, 16 p rows / block) ----------------
__global__ __launch_bounds__(256) void rowsum_kernel() {
    int b = blockIdx.y;
    int p0 = blockIdx.x * 16;
    int tid = threadIdx.x;

    __shared__ float smu[16][4];
    if (tid < 16) {
        float4 v = g_mu4[b * KK + p0 + tid];
        smu[tid][0] = v.x; smu[tid][1] = v.y; smu[tid][2] = v.z; smu[tid][3] = v.w;
    }
    __syncthreads();

    ull muPP[8][4];
#pragma unroll
    for (int j = 0; j < 8; j++)
#pragma unroll
        for (int n = 0; n < 4; n++) muPP[j][n] = pack2(smu[2 * j][n], smu[2 * j + 1][n]);

    float acc[16];
#pragma unroll
    for (int j = 0; j < 16; j++) acc[j] = 0.0f;

    for (int m = tid; m < KK; m += 256) {
        const float* c = g_pp + (size_t)(b * KK + m) * 12;
        float4 cm = *(const float4*)c;
        float4 cs = *(const float4*)(c + 4);
        float w = c[8];
        ull nm0 = splat2(-cm.x), nm1 = splat2(-cm.y), nm2 = splat2(-cm.z), nm3 = splat2(-cm.w);
        ull s0 = splat2(cs.x), s1 = splat2(cs.y), s2 = splat2(cs.z), s3 = splat2(cs.w);
#pragma unroll
        for (int j = 0; j < 8; j++) {
            ull d0 = add2(muPP[j][0], nm0);
            ull d1 = add2(muPP[j][1], nm1);
            ull d2 = add2(muPP[j][2], nm2);
            ull d3 = add2(muPP[j][3], nm3);
            ull q = mul2(mul2(fma2(d0, d0, s0), fma2(d1, d1, s1)),
                         mul2(fma2(d2, d2, s2), fma2(d3, d3, s3)));
            float ql, qh; unpack2(q, ql, qh);
            acc[2 * j]     = fmaf(w, frcp(ql), acc[2 * j]);
            acc[2 * j + 1] = fmaf(w, frcp(qh), acc[2 * j + 1]);
        }
    }

    __shared__ float red[8][17];
    int lane = tid & 31, wid = tid >> 5;
#pragma unroll
    for (int j = 0; j < 16; j++) {
        float v = acc[j];
#pragma unroll
        for (int o = 16; o > 0; o >>= 1) v += __shfl_xor_sync(0xffffffffu, v, o);
        if (lane == 0) red[wid][j] = v;
    }
    __syncthreads();
    if (tid < 16) {
        float s = 0.0f;
#pragma unroll
        for (int w = 0; w < 8; w++) s += red[w][tid];
        g_rinv[b * KK + p0 + tid] = 1.0f / s;
    }
}

// ---------------- K3: A -> MMA-fragment-packed layout ----------------
__global__ void aprep_kernel(const float* __restrict__ x) {
    int kb = blockIdx.x, b = blockIdx.y;
    int t = threadIdx.x;           // 0..191
    int mfg = t >> 5, lane = t & 31;
    int g = lane >> 2, c = lane & 3;
    int m = mfg * 16 + g;
    int k = kb * 8 + c;

    float r0 = g_rinv[b * KK + k];
    float r1 = g_rinv[b * KK + k + 4];
    const float* xb = x + (size_t)b * DD * KK;

    float4 v = make_float4(0.0f, 0.0f, 0.0f, 0.0f);
    if (m < DD) {
        v.x = to_tf32(xb[(size_t)m * KK + k] * r0);
        v.z = to_tf32(xb[(size_t)m * KK + k + 4] * r1);
    }
    if (m + 8 < DD) {
        v.y = to_tf32(xb[(size_t)(m + 8) * KK + k] * r0);
        v.w = to_tf32(xb[(size_t)(m + 8) * KK + k + 4] * r1);
    }
    *(float4*)(g_A + (((size_t)(b * 256 + kb) * 6 + mfg) * 128 + lane * 4)) = v;
}

// ---------------- K4: fused GEMM, fat warp tiles, gen/MMA interleaved ----------------
// grid (KK/NTILE=8, KSPLIT=4, BN=4) = 128 CTAs, 256 threads (8 warps = 2M x 4N).
// Warp tile 48 x 64. Gen: thread owns col pair 2*(tid&127), p-half (tid>>7)*32.
__global__ __launch_bounds__(256, 1) void gemm_fused() {
    extern __shared__ char dsm[];
    uint32_t sbase = smem_u32(dsm);

    int tid = threadIdx.x, wid = tid >> 5, lane = tid & 31;
    int n0 = blockIdx.x * NTILE, ks = blockIdx.y, b = blockIdx.z;
    int kb0 = ks * (KSEG / 8);          // global A kb base

    // ---- gen params: columns (n0 + c2, n0 + c2 + 1), p-half phalf ----
    int c2 = 2 * (tid & 127);
    int phalf = (tid >> 7) * 32;
    ull nmu[4], s2v[4];
    float w0, w1;
    {
        const float* cp = g_pp + (size_t)(b * KK + n0 + c2) * 12;
#pragma unroll
        for (int n = 0; n < 4; n++) {
            nmu[n] = pack2(-cp[n], -cp[12 + n]);
            s2v[n] = pack2(cp[4 + n], cp[16 + n]);
        }
        w0 = cp[8]; w1 = cp[20];
    }

    // ---- MMA state: warp grid 2M x 4N, warp tile 48 x 64 ----
    int warpM = wid >> 2, warpN = wid & 3;
    int nbase = warpN * 64;
    int g = lane >> 2, c = lane & 3;
    float acc[3][8][4];
#pragma unroll
    for (int i = 0; i < 3; i++)
#pragma unroll
        for (int j = 0; j < 8; j++)
#pragma unroll
            for (int q = 0; q < 4; q++) acc[i][j][q] = 0.0f;

    const float4* gA = (const float4*)(g_A + (size_t)b * 256 * 6 * 128);
    const float4* gP = &g_mu4[b * KK + ks * KSEG];

    auto cp_stage = [&](int s) {
        uint32_t ab = sbase + (uint32_t)(s % 3) * APB;
        const float4* srcA = gA + (size_t)(kb0 + s * 8) * 192;
#pragma unroll
        for (int e = 0; e < 6; e++) {
            int i = tid + 256 * e;
            cpasync16(ab + (uint32_t)i * 16u, srcA + i);
        }
        if (tid < 64)
            cpasync16(ab + ABYTES + (uint32_t)tid * 16u, gP + s * 64 + tid);
        CP_COMMIT();
    };

    // gen chunk: 4 p-rows of stage s for this thread's p-half
    auto gen_chunk = [&](int s, int kb) {
        float* Bs = (float*)(dsm + BBASE + (size_t)(s & 1) * BBYTES);
        const float* P = (const float*)(dsm + (size_t)(s % 3) * APB + ABYTES);
#pragma unroll
        for (int i = 0; i < 4; i++) {
            int p = phalf + kb * 4 + i;
            float4 mp = *(const float4*)(P + p * 4);
            ull d0 = add2(splat2(mp.x), nmu[0]);
            ull d1 = add2(splat2(mp.y), nmu[1]);
            ull d2 = add2(splat2(mp.z), nmu[2]);
            ull d3 = add2(splat2(mp.w), nmu[3]);
            ull q = mul2(mul2(fma2(d0, d0, s2v[0]), fma2(d1, d1, s2v[1])),
                         mul2(fma2(d2, d2, s2v[2]), fma2(d3, d3, s2v[3])));
            float ql, qh; unpack2(q, ql, qh);
            *(float2*)(Bs + p * BSTRIDE + c2) =
                make_float2(to_tf32(w0 * frcp(ql)), to_tf32(w1 * frcp(qh)));
        }
    };

    auto mma_kb = [&](int s, int kb) {
        const float4* A4 = (const float4*)(dsm + (size_t)(s % 3) * APB);
        const float* B = (const float*)(dsm + BBASE + (size_t)(s & 1) * BBYTES);
        uint32_t af[3][4], bf[8][2];
#pragma unroll
        for (int mf = 0; mf < 3; mf++) {
            float4 av = A4[(kb * 6 + warpM * 3 + mf) * 32 + lane];
            af[mf][0] = __float_as_uint(av.x);
            af[mf][1] = __float_as_uint(av.y);
            af[mf][2] = __float_as_uint(av.z);
            af[mf][3] = __float_as_uint(av.w);
        }
        const float* Br0 = B + (kb * 8 + c) * BSTRIDE + nbase + g;
        const float* Br1 = B + (kb * 8 + c + 4) * BSTRIDE + nbase + g;
#pragma unroll
        for (int nf = 0; nf < 8; nf++) {
            bf[nf][0] = __float_as_uint(Br0[nf * 8]);
            bf[nf][1] = __float_as_uint(Br1[nf * 8]);
        }
#pragma unroll
        for (int mf = 0; mf < 3; mf++)
#pragma unroll
            for (int nf = 0; nf < 8; nf++)
                mma_tf32(acc[mf][nf], af[mf], bf[nf]);
    };

    // ---- prologue ----
    cp_stage(0);
    cp_stage(1);
    CP_WAIT(1);          // group 0 done (A0 + P0)
    __syncthreads();
#pragma unroll
    for (int kb = 0; kb < 8; kb++) gen_chunk(0, kb);
    __syncthreads();

    // ---- main loop ----
    for (int s = 0; s < NSTG; s++) {
        if (s + 2 < NSTG) cp_stage(s + 2);
        CP_WAIT(1);      // stage s+1 (A, P) arrived; s+2 may be in flight
        if (s + 1 < NSTG) {
#pragma unroll
            for (int kb = 0; kb < 8; kb++) {
                gen_chunk(s + 1, kb);   // fma/mufu pipes
                mma_kb(s, kb);          // tensor + smem pipes
            }
        } else {
#pragma unroll
            for (int kb = 0; kb < 8; kb++) mma_kb(s, kb);
        }
        __syncthreads();
    }

    // ---- epilogue: split-K partials ----
    float* pp = g_part + ((size_t)(ks * BN + b) * MPAD) * KK + n0;
    int tig = lane & 3;
#pragma unroll
    for (int mf = 0; mf < 3; mf++) {
        int r0 = warpM * 48 + mf * 16 + g;
#pragma unroll
        for (int nf = 0; nf < 8; nf++) {
            int cc = nbase + nf * 8 + tig * 2;
            *(float2*)(pp + (size_t)r0 * KK + cc)       = make_float2(acc[mf][nf][0], acc[mf][nf][1]);
            *(float2*)(pp + (size_t)(r0 + 8) * KK + cc) = make_float2(acc[mf][nf][2], acc[mf][nf][3]);
        }
    }
}

// ---------------- K5: deterministic split-K reduce (float4) ----------------
__global__ void reduce_kernel(float* __restrict__ y) {
    int i = blockIdx.x * 256 + threadIdx.x;   // float4 index
    const int total = BN * DD * KK / 4;
    if (i >= total) return;
    int e = i * 4;
    int b = e / (DD * KK);
    int r = e - b * (DD * KK);
    int d = r / KK;
    int m = r - d * KK;
    size_t o = (((size_t)b * MPAD + d) * KK + m) / 4;
    const size_t slice = (size_t)BN * MPAD * KK / 4;
    const float4* p = (const float4*)g_part;
    float4 v0 = p[o], v1 = p[o + slice], v2 = p[o + 2 * slice], v3 = p[o + 3 * slice];
    ((float4*)y)[i] = make_float4(v0.x + v1.x + v2.x + v3.x,
                                  v0.y + v1.y + v2.y + v3.y,
                                  v0.z + v1.z + v2.z + v3.z,
                                  v0.w + v1.w + v2.w + v3.w);
}

// ---------------- launch ----------------
extern "C" void kernel_launch(void* const* d_in, const int* in_sizes, int n_in,
                              void* d_out, int out_size) {
    const float* x   = (const float*)d_in[0];  // (B, D, K)
    const float* pi  = (const float*)d_in[1];  // (B, 1, K)
    const float* mu  = (const float*)d_in[2];  // (B, ND, K)
    const float* sig = (const float*)d_in[3];  // (B, ND, K)
    float* y = (float*)d_out;                  // (B, D, K)

    cudaFuncSetAttribute(gemm_fused, cudaFuncAttributeMaxDynamicSharedMemorySize, DYN_SMEM);

    prep_kernel<<<(BN * KK + 255) / 256, 256>>>(pi, mu, sig);
    rowsum_kernel<<<dim3(KK / 16, BN), 256>>>();
    aprep_kernel<<<dim3(KK / 8, BN), 192>>>(x);
    gemm_fused<<<dim3(KK / NTILE, KSPLIT, BN), 256, DYN_SMEM>>>();
    reduce_kernel<<<(BN * DD * KK / 4 + 255) / 256, 256>>>(y);
}

// round 8
// speedup vs baseline: 1.8908x; 1.0462x over previous
#include <cuda_runtime.h>
#include <stdint.h>

// ---------------- problem constants ----------------
#define BN 4
#define DD 81
#define KK 2048
#define ND 4

// ---------------- fused GEMM config ----------------
#define MPAD 96             // padded M (81 -> 96)
#define NTILE 256           // n (components) per CTA
#define KCH 64              // k (p points) per stage
#define KSPLIT 4
#define KSEG (KK / KSPLIT)  // 512
#define NSTG (KSEG / KCH)   // 8 stages
#define BSTRIDE 264         // smem f32 row stride for B (264 mod 32 = 8 -> conflict-free frags)
#define ABYTES 24576        // (KCH/8)*6*512 frag-packed A stage
#define PBYTES 1024         // 64 x float4 mu_p
#define APB (ABYTES + PBYTES)        // 25600, triple buffered
#define BBYTES (KCH * BSTRIDE * 4)   // 67584, double buffered
#define BBASE (3 * APB)              // 76800
#define DYN_SMEM (BBASE + 2 * BBYTES)  // 211968

// ---------------- static device scratch ----------------
__device__ float  g_pp[(size_t)BN * KK * 12];           // {mu[4], sig2[4], w, pad[3]}
__device__ float4 g_mu4[BN * KK];                       // compact mu rows
__device__ float  g_rinv[BN * KK];
__device__ float  g_A[(size_t)BN * (KK / 8) * 6 * 128]; // frag-packed A
__device__ float  g_part[(size_t)KSPLIT * BN * MPAD * KK]; // split-K partials

// ---------------- helpers ----------------
typedef unsigned long long ull;
__device__ __forceinline__ float to_tf32(float v) {
    float r; asm("cvt.rna.tf32.f32 %0, %1;" : "=f"(r) : "f"(v)); return r;
}
__device__ __forceinline__ float frcp(float v) {
    float r; asm("rcp.approx.ftz.f32 %0, %1;" : "=f"(r) : "f"(v)); return r;
}
__device__ __forceinline__ ull pack2(float lo, float hi) {
    ull r; asm("mov.b64 %0, {%1, %2};" : "=l"(r) : "f"(lo), "f"(hi)); return r;
}
__device__ __forceinline__ ull splat2(float v) {
    ull r; asm("mov.b64 %0, {%1, %1};" : "=l"(r) : "f"(v)); return r;
}
__device__ __forceinline__ void unpack2(ull v, float& lo, float& hi) {
    asm("mov.b64 {%0, %1}, %2;" : "=f"(lo), "=f"(hi) : "l"(v));
}
__device__ __forceinline__ ull add2(ull a, ull b) {
    ull r; asm("add.rn.f32x2 %0, %1, %2;" : "=l"(r) : "l"(a), "l"(b)); return r;
}
__device__ __forceinline__ ull mul2(ull a, ull b) {
    ull r; asm("mul.rn.f32x2 %0, %1, %2;" : "=l"(r) : "l"(a), "l"(b)); return r;
}
__device__ __forceinline__ ull fma2(ull a, ull b, ull c) {
    ull r; asm("fma.rn.f32x2 %0, %1, %2, %3;" : "=l"(r) : "l"(a), "l"(b), "l"(c)); return r;
}
__device__ __forceinline__ uint32_t smem_u32(const void* p) {
    uint32_t a;
    asm("{ .reg .u64 t; cvta.to.shared.u64 t, %1; cvt.u32.u64 %0, t; }" : "=r"(a) : "l"(p));
    return a;
}
__device__ __forceinline__ void cpasync16(uint32_t dst, const void* src) {
    asm volatile("cp.async.cg.shared.global [%0], [%1], 16;" :: "r"(dst), "l"(src));
}
#define CP_COMMIT() asm volatile("cp.async.commit_group;" ::: "memory")
#define CP_WAIT(n)  asm volatile("cp.async.wait_group %0;" :: "n"(n) : "memory")

__device__ __forceinline__ void mma_tf32(float* d, const uint32_t* a, const uint32_t* b) {
    asm volatile(
        "mma.sync.aligned.m16n8k8.row.col.f32.tf32.tf32.f32 "
        "{%0,%1,%2,%3}, {%4,%5,%6,%7}, {%8,%9}, {%0,%1,%2,%3};"
        : "+f"(d[0]), "+f"(d[1]), "+f"(d[2]), "+f"(d[3])
        : "r"(a[0]), "r"(a[1]), "r"(a[2]), "r"(a[3]), "r"(b[0]), "r"(b[1]));
}

// ---------------- K1: pack params ----------------
__global__ void prep_kernel(const float* __restrict__ pi,
                            const float* __restrict__ mu,
                            const float* __restrict__ sig) {
    int i = blockIdx.x * 256 + threadIdx.x;
    if (i >= BN * KK) return;
    int b = i / KK, k = i - b * KK;
    float mv[4], sv[4], prod = 1.0f;
#pragma unroll
    for (int n = 0; n < ND; n++) {
        mv[n] = mu[(b * ND + n) * KK + k];
        float s = sig[(b * ND + n) * KK + k];
        sv[n] = s * s;
        prod *= s;
    }
    float* dst = g_pp + (size_t)i * 12;
    *(float4*)(dst + 0) = make_float4(mv[0], mv[1], mv[2], mv[3]);
    *(float4*)(dst + 4) = make_float4(sv[0], sv[1], sv[2], sv[3]);
    *(float4*)(dst + 8) = make_float4(pi[i] * prod, 0.0f, 0.0f, 0.0f);
    g_mu4[i] = make_float4(mv[0], mv[1], mv[2], mv[3]);
}

// ---------------- K2: row sums (f32x2-packed, 16 p rows / block) ----------------
__global__ __launch_bounds__(256) void rowsum_kernel() {
    int b = blockIdx.y;
    int p0 = blockIdx.x * 16;
    int tid = threadIdx.x;

    __shared__ float smu[16][4];
    if (tid < 16) {
        float4 v = g_mu4[b * KK + p0 + tid];
        smu[tid][0] = v.x; smu[tid][1] = v.y; smu[tid][2] = v.z; smu[tid][3] = v.w;
    }
    __syncthreads();

    ull muPP[8][4];
#pragma unroll
    for (int j = 0; j < 8; j++)
#pragma unroll
        for (int n = 0; n < 4; n++) muPP[j][n] = pack2(smu[2 * j][n], smu[2 * j + 1][n]);

    float acc[16];
#pragma unroll
    for (int j = 0; j < 16; j++) acc[j] = 0.0f;

    for (int m = tid; m < KK; m += 256) {
        const float* c = g_pp + (size_t)(b * KK + m) * 12;
        float4 cm = *(const float4*)c;
        float4 cs = *(const float4*)(c + 4);
        float w = c[8];
        ull nm0 = splat2(-cm.x), nm1 = splat2(-cm.y), nm2 = splat2(-cm.z), nm3 = splat2(-cm.w);
        ull s0 = splat2(cs.x), s1 = splat2(cs.y), s2 = splat2(cs.z), s3 = splat2(cs.w);
#pragma unroll
        for (int j = 0; j < 8; j++) {
            ull d0 = add2(muPP[j][0], nm0);
            ull d1 = add2(muPP[j][1], nm1);
            ull d2 = add2(muPP[j][2], nm2);
            ull d3 = add2(muPP[j][3], nm3);
            ull q = mul2(mul2(fma2(d0, d0, s0), fma2(d1, d1, s1)),
                         mul2(fma2(d2, d2, s2), fma2(d3, d3, s3)));
            float ql, qh; unpack2(q, ql, qh);
            acc[2 * j]     = fmaf(w, frcp(ql), acc[2 * j]);
            acc[2 * j + 1] = fmaf(w, frcp(qh), acc[2 * j + 1]);
        }
    }

    __shared__ float red[8][17];
    int lane = tid & 31, wid = tid >> 5;
#pragma unroll
    for (int j = 0; j < 16; j++) {
        float v = acc[j];
#pragma unroll
        for (int o = 16; o > 0; o >>= 1) v += __shfl_xor_sync(0xffffffffu, v, o);
        if (lane == 0) red[wid][j] = v;
    }
    __syncthreads();
    if (tid < 16) {
        float s = 0.0f;
#pragma unroll
        for (int w = 0; w < 8; w++) s += red[w][tid];
        g_rinv[b * KK + p0 + tid] = 1.0f / s;
    }
}

// ---------------- K3: A -> MMA-fragment-packed layout ----------------
__global__ void aprep_kernel(const float* __restrict__ x) {
    int kb = blockIdx.x, b = blockIdx.y;
    int t = threadIdx.x;           // 0..191
    int mfg = t >> 5, lane = t & 31;
    int g = lane >> 2, c = lane & 3;
    int m = mfg * 16 + g;
    int k = kb * 8 + c;

    float r0 = g_rinv[b * KK + k];
    float r1 = g_rinv[b * KK + k + 4];
    const float* xb = x + (size_t)b * DD * KK;

    float4 v = make_float4(0.0f, 0.0f, 0.0f, 0.0f);
    if (m < DD) {
        v.x = to_tf32(xb[(size_t)m * KK + k] * r0);
        v.z = to_tf32(xb[(size_t)m * KK + k + 4] * r1);
    }
    if (m + 8 < DD) {
        v.y = to_tf32(xb[(size_t)(m + 8) * KK + k] * r0);
        v.w = to_tf32(xb[(size_t)(m + 8) * KK + k + 4] * r1);
    }
    *(float4*)(g_A + (((size_t)(b * 256 + kb) * 6 + mfg) * 128 + lane * 4)) = v;
}

// ---------------- K4: fused GEMM, 16 warps, warp tile 48x32, gen/MMA interleaved ----------------
// grid (KK/NTILE=8, KSPLIT=4, BN=4) = 128 CTAs, 512 threads (16 warps = 2M x 8N).
__global__ __launch_bounds__(512, 1) void gemm_fused() {
    extern __shared__ char dsm[];
    uint32_t sbase = smem_u32(dsm);

    int tid = threadIdx.x, wid = tid >> 5, lane = tid & 31;
    int n0 = blockIdx.x * NTILE, ks = blockIdx.y, b = blockIdx.z;
    int kb0 = ks * (KSEG / 8);          // global A kb base

    // ---- gen params: columns (n0 + c2, n0 + c2 + 1), p-quarter pq ----
    int c2 = 2 * (tid & 127);
    int pq = (tid >> 7) * 16;           // 0,16,32,48
    ull nmu[4], s2v[4];
    float w0, w1;
    {
        const float* cp = g_pp + (size_t)(b * KK + n0 + c2) * 12;
#pragma unroll
        for (int n = 0; n < 4; n++) {
            nmu[n] = pack2(-cp[n], -cp[12 + n]);
            s2v[n] = pack2(cp[4 + n], cp[16 + n]);
        }
        w0 = cp[8]; w1 = cp[20];
    }

    // ---- MMA state: warp grid 2M x 8N, warp tile 48 x 32 ----
    int warpM = wid >> 3, warpN = wid & 7;
    int nbase = warpN * 32;
    int g = lane >> 2, c = lane & 3;
    float acc[3][4][4];
#pragma unroll
    for (int i = 0; i < 3; i++)
#pragma unroll
        for (int j = 0; j < 4; j++)
#pragma unroll
            for (int q = 0; q < 4; q++) acc[i][j][q] = 0.0f;

    const float4* gA = (const float4*)(g_A + (size_t)b * 256 * 6 * 128);
    const float4* gP = &g_mu4[b * KK + ks * KSEG];

    auto cp_stage = [&](int s) {
        uint32_t ab = sbase + (uint32_t)(s % 3) * APB;
        const float4* srcA = gA + (size_t)(kb0 + s * 8) * 192;
#pragma unroll
        for (int e = 0; e < 3; e++) {
            int i = tid + 512 * e;
            cpasync16(ab + (uint32_t)i * 16u, srcA + i);
        }
        if (tid < 64)
            cpasync16(ab + ABYTES + (uint32_t)tid * 16u, gP + s * 64 + tid);
        CP_COMMIT();
    };

    // gen chunk: 2 p-rows of stage s for this thread (p = pq + kb*2 + {0,1})
    auto gen_chunk = [&](int s, int kb) {
        float* Bs = (float*)(dsm + BBASE + (size_t)(s & 1) * BBYTES);
        const float* P = (const float*)(dsm + (size_t)(s % 3) * APB + ABYTES);
#pragma unroll
        for (int i = 0; i < 2; i++) {
            int p = pq + kb * 2 + i;
            float4 mp = *(const float4*)(P + p * 4);
            ull d0 = add2(splat2(mp.x), nmu[0]);
            ull d1 = add2(splat2(mp.y), nmu[1]);
            ull d2 = add2(splat2(mp.z), nmu[2]);
            ull d3 = add2(splat2(mp.w), nmu[3]);
            ull q = mul2(mul2(fma2(d0, d0, s2v[0]), fma2(d1, d1, s2v[1])),
                         mul2(fma2(d2, d2, s2v[2]), fma2(d3, d3, s2v[3])));
            float ql, qh; unpack2(q, ql, qh);
            *(float2*)(Bs + p * BSTRIDE + c2) =
                make_float2(to_tf32(w0 * frcp(ql)), to_tf32(w1 * frcp(qh)));
        }
    };

    auto mma_kb = [&](int s, int kb) {
        const float4* A4 = (const float4*)(dsm + (size_t)(s % 3) * APB);
        const float* B = (const float*)(dsm + BBASE + (size_t)(s & 1) * BBYTES);
        uint32_t af[3][4], bf[4][2];
#pragma unroll
        for (int mf = 0; mf < 3; mf++) {
            float4 av = A4[(kb * 6 + warpM * 3 + mf) * 32 + lane];
            af[mf][0] = __float_as_uint(av.x);
            af[mf][1] = __float_as_uint(av.y);
            af[mf][2] = __float_as_uint(av.z);
            af[mf][3] = __float_as_uint(av.w);
        }
        const float* Br0 = B + (kb * 8 + c) * BSTRIDE + nbase + g;
        const float* Br1 = B + (kb * 8 + c + 4) * BSTRIDE + nbase + g;
#pragma unroll
        for (int nf = 0; nf < 4; nf++) {
            bf[nf][0] = __float_as_uint(Br0[nf * 8]);
            bf[nf][1] = __float_as_uint(Br1[nf * 8]);
        }
#pragma unroll
        for (int mf = 0; mf < 3; mf++)
#pragma unroll
            for (int nf = 0; nf < 4; nf++)
                mma_tf32(acc[mf][nf], af[mf], bf[nf]);
    };

    // ---- prologue ----
    cp_stage(0);
    cp_stage(1);
    CP_WAIT(1);          // group 0 done (A0 + P0)
    __syncthreads();
#pragma unroll
    for (int kb = 0; kb < 8; kb++) gen_chunk(0, kb);
    __syncthreads();

    // ---- main loop: cp(s+2) || gen(s+1) || MMA(s), one barrier per stage ----
    for (int s = 0; s < NSTG; s++) {
        if (s + 2 < NSTG) cp_stage(s + 2);
        CP_WAIT(1);      // stage s+1 (A, P) arrived; s+2 may be in flight
        if (s + 1 < NSTG) {
#pragma unroll
            for (int kb = 0; kb < 8; kb++) {
                gen_chunk(s + 1, kb);   // fma/mufu pipes
                mma_kb(s, kb);          // tensor + smem pipes
            }
        } else {
#pragma unroll
            for (int kb = 0; kb < 8; kb++) mma_kb(s, kb);
        }
        __syncthreads();
    }

    // ---- epilogue: split-K partials ----
    float* pp = g_part + ((size_t)(ks * BN + b) * MPAD) * KK + n0;
    int tig = lane & 3;
#pragma unroll
    for (int mf = 0; mf < 3; mf++) {
        int r0 = warpM * 48 + mf * 16 + g;
#pragma unroll
        for (int nf = 0; nf < 4; nf++) {
            int cc = nbase + nf * 8 + tig * 2;
            *(float2*)(pp + (size_t)r0 * KK + cc)       = make_float2(acc[mf][nf][0], acc[mf][nf][1]);
            *(float2*)(pp + (size_t)(r0 + 8) * KK + cc) = make_float2(acc[mf][nf][2], acc[mf][nf][3]);
        }
    }
}

// ---------------- K5: deterministic split-K reduce (float4) ----------------
__global__ void reduce_kernel(float* __restrict__ y) {
    int i = blockIdx.x * 256 + threadIdx.x;   // float4 index
    const int total = BN * DD * KK / 4;
    if (i >= total) return;
    int e = i * 4;
    int b = e / (DD * KK);
    int r = e - b * (DD * KK);
    int d = r / KK;
    int m = r - d * KK;
    size_t o = (((size_t)b * MPAD + d) * KK + m) / 4;
    const size_t slice = (size_t)BN * MPAD * KK / 4;
    const float4* p = (const float4*)g_part;
    float4 v0 = p[o], v1 = p[o + slice], v2 = p[o + 2 * slice], v3 = p[o + 3 * slice];
    ((float4*)y)[i] = make_float4(v0.x + v1.x + v2.x + v3.x,
                                  v0.y + v1.y + v2.y + v3.y,
                                  v0.z + v1.z + v2.z + v3.z,
                                  v0.w + v1.w + v2.w + v3.w);
}

// ---------------- launch ----------------
extern "C" void kernel_launch(void* const* d_in, const int* in_sizes, int n_in,
                              void* d_out, int out_size) {
    const float* x   = (const float*)d_in[0];  // (B, D, K)
    const float* pi  = (const float*)d_in[1];  // (B, 1, K)
    const float* mu  = (const float*)d_in[2];  // (B, ND, K)
    const float* sig = (const float*)d_in[3];  // (B, ND, K)
    float* y = (float*)d_out;                  // (B, D, K)

    cudaFuncSetAttribute(gemm_fused, cudaFuncAttributeMaxDynamicSharedMemorySize, DYN_SMEM);

    prep_kernel<<<(BN * KK + 255) / 256, 256>>>(pi, mu, sig);
    rowsum_kernel<<<dim3(KK / 16, BN), 256>>>();
    aprep_kernel<<<dim3(KK / 8, BN), 192>>>(x);
    gemm_fused<<<dim3(KK / NTILE, KSPLIT, BN), 512, DYN_SMEM>>>();
    reduce_kernel<<<(BN * DD * KK / 4 + 255) / 256, 256>>>(y);
}

// round 9
// speedup vs baseline: 2.3026x; 1.2178x over previous
#include <cuda_runtime.h>
#include <stdint.h>

// ---------------- problem constants ----------------
#define BN 4
#define DD 81
#define KK 2048
#define ND 4

// ---------------- fused GEMM config (fp16 m16n8k16) ----------------
#define MPAD 96             // padded M (81 -> 96)
#define NTILE 256           // n (components) per CTA
#define KCH 64              // k (p points) per stage
#define KSPLIT 4
#define KSEG (KK / KSPLIT)  // 512
#define NSTG (KSEG / KCH)   // 8 stages
#define NSTRIDE 264         // u32 words per kpair row (264 mod 32 = 8 -> conflict-free)
#define ABYTES 12288        // 4 kb16 x 6 fragrows x 512B (fp16 frag-packed A)
#define APB 13824           // A + mu4(1024) + rinv(256) + pad, triple buffered
#define BBYTES (32 * NSTRIDE * 4)   // 33792, double buffered
#define BBASE (3 * APB)             // 41472
#define DYN_SMEM (BBASE + 2 * BBYTES)  // 109056

// ---------------- static device scratch ----------------
__device__ float    g_pp[(size_t)BN * KK * 12];           // {mu[4], sig2[4], w, pad[3]}
__device__ float4   g_mu4[BN * KK];                       // compact mu rows
__device__ float    g_rinv[BN * KK];
__device__ uint32_t g_Ah[(size_t)BN * 128 * 6 * 128];     // fp16 frag-packed A (x only)
__device__ float    g_part[(size_t)KSPLIT * BN * MPAD * KK]; // split-K partials

// ---------------- helpers ----------------
typedef unsigned long long ull;
__device__ __forceinline__ float frcp(float v) {
    float r; asm("rcp.approx.ftz.f32 %0, %1;" : "=f"(r) : "f"(v)); return r;
}
__device__ __forceinline__ uint32_t f16x2(float lo, float hi) {
    uint32_t r; asm("cvt.rn.f16x2.f32 %0, %1, %2;" : "=r"(r) : "f"(hi), "f"(lo)); return r;
}
__device__ __forceinline__ ull pack2(float lo, float hi) {
    ull r; asm("mov.b64 %0, {%1, %2};" : "=l"(r) : "f"(lo), "f"(hi)); return r;
}
__device__ __forceinline__ ull splat2(float v) {
    ull r; asm("mov.b64 %0, {%1, %1};" : "=l"(r) : "f"(v)); return r;
}
__device__ __forceinline__ void unpack2(ull v, float& lo, float& hi) {
    asm("mov.b64 {%0, %1}, %2;" : "=f"(lo), "=f"(hi) : "l"(v));
}
__device__ __forceinline__ ull add2(ull a, ull b) {
    ull r; asm("add.rn.f32x2 %0, %1, %2;" : "=l"(r) : "l"(a), "l"(b)); return r;
}
__device__ __forceinline__ ull mul2(ull a, ull b) {
    ull r; asm("mul.rn.f32x2 %0, %1, %2;" : "=l"(r) : "l"(a), "l"(b)); return r;
}
__device__ __forceinline__ ull fma2(ull a, ull b, ull c) {
    ull r; asm("fma.rn.f32x2 %0, %1, %2, %3;" : "=l"(r) : "l"(a), "l"(b), "l"(c)); return r;
}
__device__ __forceinline__ uint32_t smem_u32(const void* p) {
    uint32_t a;
    asm("{ .reg .u64 t; cvta.to.shared.u64 t, %1; cvt.u32.u64 %0, t; }" : "=r"(a) : "l"(p));
    return a;
}
__device__ __forceinline__ void cpasync16(uint32_t dst, const void* src) {
    asm volatile("cp.async.cg.shared.global [%0], [%1], 16;" :: "r"(dst), "l"(src));
}
#define CP_COMMIT() asm volatile("cp.async.commit_group;" ::: "memory")
#define CP_WAIT(n)  asm volatile("cp.async.wait_group %0;" :: "n"(n) : "memory")

__device__ __forceinline__ void mma_f16(float* d, const uint32_t* a, const uint32_t* b) {
    asm volatile(
        "mma.sync.aligned.m16n8k16.row.col.f32.f16.f16.f32 "
        "{%0,%1,%2,%3}, {%4,%5,%6,%7}, {%8,%9}, {%0,%1,%2,%3};"
        : "+f"(d[0]), "+f"(d[1]), "+f"(d[2]), "+f"(d[3])
        : "r"(a[0]), "r"(a[1]), "r"(a[2]), "r"(a[3]), "r"(b[0]), "r"(b[1]));
}

// ---------------- K1: pack params ----------------
__global__ void prep_kernel(const float* __restrict__ pi,
                            const float* __restrict__ mu,
                            const float* __restrict__ sig) {
    int i = blockIdx.x * 256 + threadIdx.x;
    if (i >= BN * KK) return;
    int b = i / KK, k = i - b * KK;
    float mv[4], sv[4], prod = 1.0f;
#pragma unroll
    for (int n = 0; n < ND; n++) {
        mv[n] = mu[(b * ND + n) * KK + k];
        float s = sig[(b * ND + n) * KK + k];
        sv[n] = s * s;
        prod *= s;
    }
    float* dst = g_pp + (size_t)i * 12;
    *(float4*)(dst + 0) = make_float4(mv[0], mv[1], mv[2], mv[3]);
    *(float4*)(dst + 4) = make_float4(sv[0], sv[1], sv[2], sv[3]);
    *(float4*)(dst + 8) = make_float4(pi[i] * prod, 0.0f, 0.0f, 0.0f);
    g_mu4[i] = make_float4(mv[0], mv[1], mv[2], mv[3]);
}

// ---------------- K2: row sums (f32x2-packed, 16 p rows / block) ----------------
__global__ __launch_bounds__(256) void rowsum_kernel() {
    int b = blockIdx.y;
    int p0 = blockIdx.x * 16;
    int tid = threadIdx.x;

    __shared__ float smu[16][4];
    if (tid < 16) {
        float4 v = g_mu4[b * KK + p0 + tid];
        smu[tid][0] = v.x; smu[tid][1] = v.y; smu[tid][2] = v.z; smu[tid][3] = v.w;
    }
    __syncthreads();

    ull muPP[8][4];
#pragma unroll
    for (int j = 0; j < 8; j++)
#pragma unroll
        for (int n = 0; n < 4; n++) muPP[j][n] = pack2(smu[2 * j][n], smu[2 * j + 1][n]);

    float acc[16];
#pragma unroll
    for (int j = 0; j < 16; j++) acc[j] = 0.0f;

    for (int m = tid; m < KK; m += 256) {
        const float* c = g_pp + (size_t)(b * KK + m) * 12;
        float4 cm = *(const float4*)c;
        float4 cs = *(const float4*)(c + 4);
        float w = c[8];
        ull nm0 = splat2(-cm.x), nm1 = splat2(-cm.y), nm2 = splat2(-cm.z), nm3 = splat2(-cm.w);
        ull s0 = splat2(cs.x), s1 = splat2(cs.y), s2 = splat2(cs.z), s3 = splat2(cs.w);
#pragma unroll
        for (int j = 0; j < 8; j++) {
            ull d0 = add2(muPP[j][0], nm0);
            ull d1 = add2(muPP[j][1], nm1);
            ull d2 = add2(muPP[j][2], nm2);
            ull d3 = add2(muPP[j][3], nm3);
            ull q = mul2(mul2(fma2(d0, d0, s0), fma2(d1, d1, s1)),
                         mul2(fma2(d2, d2, s2), fma2(d3, d3, s3)));
            float ql, qh; unpack2(q, ql, qh);
            acc[2 * j]     = fmaf(w, frcp(ql), acc[2 * j]);
            acc[2 * j + 1] = fmaf(w, frcp(qh), acc[2 * j + 1]);
        }
    }

    __shared__ float red[8][17];
    int lane = tid & 31, wid = tid >> 5;
#pragma unroll
    for (int j = 0; j < 16; j++) {
        float v = acc[j];
#pragma unroll
        for (int o = 16; o > 0; o >>= 1) v += __shfl_xor_sync(0xffffffffu, v, o);
        if (lane == 0) red[wid][j] = v;
    }
    __syncthreads();
    if (tid < 16) {
        float s = 0.0f;
#pragma unroll
        for (int w = 0; w < 8; w++) s += red[w][tid];
        g_rinv[b * KK + p0 + tid] = 1.0f / s;
    }
}

// ---------------- K3: A (raw x) -> fp16 m16n8k16 frag-packed layout ----------------
// grid (128 kb16, BN), 192 threads. No rinv (folded into B).
__global__ void aprep_kernel(const float* __restrict__ x) {
    int kb = blockIdx.x, b = blockIdx.y;
    int t = threadIdx.x;
    int mfg = t >> 5, lane = t & 31;
    int g = lane >> 2, c = lane & 3;
    int m0 = mfg * 16 + g, m1 = m0 + 8;
    int k0 = kb * 16 + 2 * c;

    const float* xb = x + (size_t)b * DD * KK;
    float2 z = make_float2(0.0f, 0.0f);
    float2 xa = (m0 < DD) ? *(const float2*)(xb + (size_t)m0 * KK + k0)     : z;
    float2 xb2 = (m0 < DD) ? *(const float2*)(xb + (size_t)m0 * KK + k0 + 8) : z;
    float2 xc = (m1 < DD) ? *(const float2*)(xb + (size_t)m1 * KK + k0)     : z;
    float2 xd = (m1 < DD) ? *(const float2*)(xb + (size_t)m1 * KK + k0 + 8) : z;

    uint4 out;
    out.x = f16x2(xa.x, xa.y);   // a0: row m0, k low
    out.y = f16x2(xc.x, xc.y);   // a1: row m1, k low
    out.z = f16x2(xb2.x, xb2.y); // a2: row m0, k high
    out.w = f16x2(xd.x, xd.y);   // a3: row m1, k high
    *(uint4*)(g_Ah + (((size_t)(b * 128 + kb) * 6 + mfg) * 128 + lane * 4)) = out;
}

// ---------------- K4: fused fp16 GEMM, 16 warps (2M x 8N), warp tile 48x32 ----------------
// grid (KK/NTILE=8, KSPLIT=4, BN=4) = 128 CTAs, 512 threads.
// B generated in-kernel as fp16 coef = rinv_p * w_m / q(p,m), kpair-major [kpair][n].
__global__ __launch_bounds__(512, 1) void gemm_fused() {
    extern __shared__ char dsm[];
    uint32_t sbase = smem_u32(dsm);

    int tid = threadIdx.x, wid = tid >> 5, lane = tid & 31;
    int n0 = blockIdx.x * NTILE, ks = blockIdx.y, b = blockIdx.z;
    int kb0 = ks * (KSEG / 16);         // global kb16 base (32 per split)

    // ---- gen params: column n = n0 + (tid & 255), k-half = tid >> 8 ----
    int ncol = tid & 255;
    int khalf = tid >> 8;
    ull snmu[4], s2v[4];
    float w_m;
    {
        const float* cp = g_pp + (size_t)(b * KK + n0 + ncol) * 12;
#pragma unroll
        for (int n = 0; n < 4; n++) {
            snmu[n] = splat2(-cp[n]);
            s2v[n]  = splat2(cp[4 + n]);
        }
        w_m = cp[8];
    }

    // ---- MMA state ----
    int warpM = wid >> 3, warpN = wid & 7;
    int nbase = warpN * 32;
    int g = lane >> 2, c = lane & 3;
    float acc[3][4][4];
#pragma unroll
    for (int i = 0; i < 3; i++)
#pragma unroll
        for (int j = 0; j < 4; j++)
#pragma unroll
            for (int q = 0; q < 4; q++) acc[i][j][q] = 0.0f;

    const uint4* gA = (const uint4*)(g_Ah + (size_t)b * 128 * 6 * 128);
    const float4* gP = &g_mu4[b * KK + ks * KSEG];
    const float* gRi = g_rinv + b * KK + ks * KSEG;

    auto cp_stage = [&](int s) {
        uint32_t ab = sbase + (uint32_t)(s % 3) * APB;
        const uint4* srcA = gA + (size_t)(kb0 + s * 4) * 192;
        cpasync16(ab + (uint32_t)tid * 16u, srcA + tid);
        if (tid < 256) cpasync16(ab + (uint32_t)(tid + 512) * 16u, srcA + tid + 512);
        if (tid < 64) cpasync16(ab + 12288u + (uint32_t)tid * 16u, gP + s * 64 + tid);
        if (tid < 16) cpasync16(ab + 13312u + (uint32_t)tid * 16u, gRi + s * 64 + tid * 4);
        CP_COMMIT();
    };

    // gen chunk: this thread's 4 kpairs (8 p) of stage s for kb16 'kb'
    auto gen_chunk = [&](int s, int kb) {
        uint32_t* Bs = (uint32_t*)(dsm + BBASE + (size_t)(s & 1) * BBYTES);
        const float* P = (const float*)(dsm + (size_t)(s % 3) * APB + 12288);
        const float* RI = (const float*)(dsm + (size_t)(s % 3) * APB + 13312);
#pragma unroll
        for (int i = 0; i < 4; i++) {
            int kp = kb * 8 + khalf * 4 + i;   // kpair within stage
            int p2 = kp * 2;
            float4 mp0 = *(const float4*)(P + p2 * 4);
            float4 mp1 = *(const float4*)(P + p2 * 4 + 4);
            float2 ri = *(const float2*)(RI + p2);
            ull d0 = add2(pack2(mp0.x, mp1.x), snmu[0]);
            ull d1 = add2(pack2(mp0.y, mp1.y), snmu[1]);
            ull d2 = add2(pack2(mp0.z, mp1.z), snmu[2]);
            ull d3 = add2(pack2(mp0.w, mp1.w), snmu[3]);
            ull q = mul2(mul2(fma2(d0, d0, s2v[0]), fma2(d1, d1, s2v[1])),
                         mul2(fma2(d2, d2, s2v[2]), fma2(d3, d3, s2v[3])));
            float ql, qh; unpack2(q, ql, qh);
            float v0 = w_m * ri.x * frcp(ql);
            float v1 = w_m * ri.y * frcp(qh);
            Bs[kp * NSTRIDE + ncol] = f16x2(v0, v1);
        }
    };

    auto mma_kb = [&](int s, int kb) {
        const uint4* A4 = (const uint4*)(dsm + (size_t)(s % 3) * APB);
        const uint32_t* B = (const uint32_t*)(dsm + BBASE + (size_t)(s & 1) * BBYTES);
        uint32_t af[3][4], bf[4][2];
#pragma unroll
        for (int mf = 0; mf < 3; mf++) {
            uint4 av = A4[(kb * 6 + warpM * 3 + mf) * 32 + lane];
            af[mf][0] = av.x; af[mf][1] = av.y; af[mf][2] = av.z; af[mf][3] = av.w;
        }
        const uint32_t* Br0 = B + (kb * 8 + c) * NSTRIDE + nbase + g;
        const uint32_t* Br1 = B + (kb * 8 + c + 4) * NSTRIDE + nbase + g;
#pragma unroll
        for (int nf = 0; nf < 4; nf++) {
            bf[nf][0] = Br0[nf * 8];
            bf[nf][1] = Br1[nf * 8];
        }
#pragma unroll
        for (int mf = 0; mf < 3; mf++)
#pragma unroll
            for (int nf = 0; nf < 4; nf++)
                mma_f16(acc[mf][nf], af[mf], bf[nf]);
    };

    // ---- prologue ----
    cp_stage(0);
    cp_stage(1);
    CP_WAIT(1);          // group 0 (A0, P0, rinv0) done
    __syncthreads();
#pragma unroll
    for (int kb = 0; kb < 4; kb++) gen_chunk(0, kb);
    __syncthreads();

    // ---- main loop: cp(s+2) || gen(s+1) || MMA(s) ----
    for (int s = 0; s < NSTG; s++) {
        if (s + 2 < NSTG) { cp_stage(s + 2); CP_WAIT(1); }
        else              { CP_WAIT(0); }
        if (s + 1 < NSTG) {
#pragma unroll
            for (int kb = 0; kb < 4; kb++) {
                gen_chunk(s + 1, kb);   // fma/mufu pipes
                mma_kb(s, kb);          // tensor + smem pipes
            }
        } else {
#pragma unroll
            for (int kb = 0; kb < 4; kb++) mma_kb(s, kb);
        }
        __syncthreads();
    }

    // ---- epilogue: split-K partials ----
    float* pp = g_part + ((size_t)(ks * BN + b) * MPAD) * KK + n0;
    int tig = lane & 3;
#pragma unroll
    for (int mf = 0; mf < 3; mf++) {
        int r0 = warpM * 48 + mf * 16 + g;
#pragma unroll
        for (int nf = 0; nf < 4; nf++) {
            int cc = nbase + nf * 8 + tig * 2;
            *(float2*)(pp + (size_t)r0 * KK + cc)       = make_float2(acc[mf][nf][0], acc[mf][nf][1]);
            *(float2*)(pp + (size_t)(r0 + 8) * KK + cc) = make_float2(acc[mf][nf][2], acc[mf][nf][3]);
        }
    }
}

// ---------------- K5: deterministic split-K reduce (float4) ----------------
__global__ void reduce_kernel(float* __restrict__ y) {
    int i = blockIdx.x * 256 + threadIdx.x;   // float4 index
    const int total = BN * DD * KK / 4;
    if (i >= total) return;
    int e = i * 4;
    int b = e / (DD * KK);
    int r = e - b * (DD * KK);
    int d = r / KK;
    int m = r - d * KK;
    size_t o = (((size_t)b * MPAD + d) * KK + m) / 4;
    const size_t slice = (size_t)BN * MPAD * KK / 4;
    const float4* p = (const float4*)g_part;
    float4 v0 = p[o], v1 = p[o + slice], v2 = p[o + 2 * slice], v3 = p[o + 3 * slice];
    ((float4*)y)[i] = make_float4(v0.x + v1.x + v2.x + v3.x,
                                  v0.y + v1.y + v2.y + v3.y,
                                  v0.z + v1.z + v2.z + v3.z,
                                  v0.w + v1.w + v2.w + v3.w);
}

// ---------------- launch ----------------
extern "C" void kernel_launch(void* const* d_in, const int* in_sizes, int n_in,
                              void* d_out, int out_size) {
    const float* x   = (const float*)d_in[0];  // (B, D, K)
    const float* pi  = (const float*)d_in[1];  // (B, 1, K)
    const float* mu  = (const float*)d_in[2];  // (B, ND, K)
    const float* sig = (const float*)d_in[3];  // (B, ND, K)
    float* y = (float*)d_out;                  // (B, D, K)

    cudaFuncSetAttribute(gemm_fused, cudaFuncAttributeMaxDynamicSharedMemorySize, DYN_SMEM);

    prep_kernel<<<(BN * KK + 255) / 256, 256>>>(pi, mu, sig);
    rowsum_kernel<<<dim3(KK / 16, BN), 256>>>();
    aprep_kernel<<<dim3(128, BN), 192>>>(x);
    gemm_fused<<<dim3(KK / NTILE, KSPLIT, BN), 512, DYN_SMEM>>>();
    reduce_kernel<<<(BN * DD * KK / 4 + 255) / 256, 256>>>(y);
}